// round 16
// baseline (speedup 1.0000x reference)
#include <cuda_runtime.h>
#include <math.h>

// ---------------- problem constants ----------------
#define S_NUM   16
#define O_NUM   15
#define BATCH   4096
#define N_IN    64
#define WSHAPE  3120
#define BSHAPE  41
#define TOTAL_ELEMS (S_NUM * BATCH * O_NUM)   // 983040
#define E_JOINT 41
#define SO_NUM  (S_NUM * O_NUM)               // 240
#define NTHR    128
#define PAIRS_CTA 128                         // 256 batch per CTA (4 pairs/lane)
#define NPAIR   (BATCH / 2)                   // 2048
#define NBLK_B  (NPAIR / PAIRS_CTA)           // 16
#define NPART   (SO_NUM * NBLK_B)             // 3840
#define WD_STRIDE 42                          // u64/dim row: slots 0/12/22/32
#define EPSF    1e-20f
#define TEMP    0.03f

#define NBLK_GATE ((SO_NUM * WSHAPE + 255) / 256)   // 2925
#define NBLK_TR   ((BATCH / 32) * (N_IN / 32))      // 256

typedef unsigned long long u64;

// scratch (allocation-free rule: __device__ globals)
__device__ __align__(16) float g_obsT[N_IN * BATCH];            // 1 MB
__device__ __align__(16) u64 g_wgemm[SO_NUM * 64 * WD_STRIDE];  // 5.2 MB dup'd
__device__ __align__(16) u64 g_wtail[SO_NUM * 496];             // 0.95 MB dup'd
__device__ float g_partials[NPART];

// ---------------- packed f32x2 helpers ----------------
__device__ __forceinline__ u64 pk(float lo, float hi) {
    u64 r; asm("mov.b64 %0, {%1, %2};" : "=l"(r) : "f"(lo), "f"(hi)); return r;
}
__device__ __forceinline__ float2 unpk(u64 v) {
    float2 f; asm("mov.b64 {%0, %1}, %2;" : "=f"(f.x), "=f"(f.y) : "l"(v)); return f;
}
__device__ __forceinline__ u64 dup2(float x) { return pk(x, x); }
__device__ __forceinline__ u64 ffma2(u64 a, u64 b, u64 c) {
    u64 d; asm("fma.rn.f32x2 %0, %1, %2, %3;" : "=l"(d) : "l"(a), "l"(b), "l"(c));
    return d;
}

// ---------------- phase 1 (single launch): gate->weights + obs transpose ----
// Blocks [0, NBLK_GATE): gate math (PRECISE — threshold-sensitive), scattered
// directly into final g_wgemm/g_wtail layout. GEMM slot = ej + (ej>=11):
// groups g0 ej0-10 @slot0, g1 ej11-20 @12, g2 ej21-30 @22, g3 ej31-40 @32.
// Blocks [NBLK_GATE, NBLK_GATE+NBLK_TR): tiled obs transpose into g_obsT.
__global__ void eql_prepare(const float* __restrict__ scores,
                            const float* __restrict__ base,
                            const float* __restrict__ u0,
                            const float* __restrict__ u1,
                            const float* __restrict__ obs) {
    if (blockIdx.x < NBLK_GATE) {
        int i = blockIdx.x * 256 + threadIdx.x;
        if (i >= SO_NUM * WSHAPE) return;
        int so   = i / WSHAPE;
        int widx = i % WSHAPE;
        int ow   = i % (O_NUM * WSHAPE);

        float sc    = scores[ow];
        float cs    = 1.0f / (1.0f + expf(-sc));
        float logit = logf(cs + EPSF) - logf(1.0f - cs + EPSF);
        float noise = -logf(logf(u0[i] + EPSF) / logf(u1[i] + EPSF) + EPSF);
        float z     = (logit + noise) * TEMP;
        float soft  = 1.0f / (1.0f + expf(-z));
        float hard  = (soft > 0.5f) ? 1.0f : 0.0f;
        float w     = base[ow] * ((hard - soft) + soft);

        // route widx -> (seg, d, e)
        int seg;
        if (widx < 1346) seg = (widx < 384) ? 0 : ((widx < 786) ? 1 : 2);
        else if (widx < 2486) seg = (widx < 1970) ? 3 : 4;
        else seg = (widx < 3026) ? 5 : 6;
        const int S_[7]   = {0, 384, 786, 1346, 1970, 2486, 3026};
        const int INL[7]  = {6, 6, 8, 8, 6, 6, 1};
        const int EJB_[7] = {0, 6, 12, 20, 28, 34, 40};
        const int TB_[7]  = {0, 0, 18, 66, 178, 310, 466};
        int r = widx - S_[seg];
        int d = r / INL[seg], e = r % INL[seg];
        u64 wd = dup2(w);
        if (d < 64) {
            int ej   = EJB_[seg] + e;
            int slot = ej + (ej >= 11 ? 1 : 0);
            g_wgemm[(size_t)so * (64 * WD_STRIDE) + d * WD_STRIDE + slot] = wd;
        } else {
            g_wtail[(size_t)so * 496 + TB_[seg] + (d - 64) * INL[seg] + e] = wd;
        }
    } else {
        // obs transpose: emulate (32,8) block over 256 threads
        __shared__ float tile[32][33];
        int blk = blockIdx.x - NBLK_GATE;
        int bx = (blk & (BATCH / 32 - 1)) * 32;   // batch base
        int dx = (blk >> 7) * 32;                 // dim base (BATCH/32 = 128)
        int tx = threadIdx.x & 31, ty = threadIdx.x >> 5;  // (32, 8)
        #pragma unroll
        for (int j = 0; j < 32; j += 8)
            tile[ty + j][tx] = obs[(size_t)(bx + ty + j) * N_IN + dx + tx];
        __syncthreads();
        #pragma unroll
        for (int j = 0; j < 32; j += 8)
            g_obsT[(size_t)(dx + ty + j) * BATCH + bx + tx] = tile[tx][ty + j];
    }
}

// ---------------- scalar ops (fast intrinsics; validated rel_err 3.8e-5) ---
__device__ __forceinline__ float op_mul(float a, float b, float& r) {
    r += fmaxf(-100.0f - a, 0.0f) + fmaxf(a - 100.0f, 0.0f)
       + fmaxf(-100.0f - b, 0.0f) + fmaxf(b - 100.0f, 0.0f);
    return fminf(fmaxf(a, -100.0f), 100.0f) * fminf(fmaxf(b, -100.0f), 100.0f);
}
__device__ __forceinline__ float op_div(float a, float b, float& r) {
    r += fmaxf(0.01f - b, 0.0f);
    return (b < 0.01f) ? 0.0f : __fdividef(a, b);
}
__device__ __forceinline__ float op_log(float a, float& r) {
    r += fmaxf(0.001f - a, 0.0f);
    return __logf(fmaxf(a, 0.001f));
}
__device__ __forceinline__ float op_exp(float a, float& r) {
    r += fmaxf(-10.0f - a, 0.0f) + fmaxf(a - 4.0f, 0.0f);
    return __expf(fminf(fmaxf(a, -10.0f), 4.0f));
}
__device__ __forceinline__ u64 opk_mul(u64 A, u64 B, float& r) {
    float2 a = unpk(A), b = unpk(B);
    return pk(op_mul(a.x, b.x, r), op_mul(a.y, b.y, r));
}
__device__ __forceinline__ u64 opk_div(u64 A, u64 B, float& r) {
    float2 a = unpk(A), b = unpk(B);
    return pk(op_div(a.x, b.x, r), op_div(a.y, b.y, r));
}
__device__ __forceinline__ u64 opk_log(u64 A, float& r) {
    float2 a = unpk(A); return pk(op_log(a.x, r), op_log(a.y, r));
}
__device__ __forceinline__ u64 opk_exp(u64 A, float& r) {
    float2 a = unpk(A); return pk(op_exp(a.x, r), op_exp(a.y, r));
}
__device__ __forceinline__ u64 opk_sin(u64 A) {
    float2 a = unpk(A); return pk(__sinf(a.x), __sinf(a.y));
}
__device__ __forceinline__ u64 opk_cos(u64 A) {
    float2 a = unpk(A); return pk(__cosf(a.x), __cosf(a.y));
}

// ---------------- GEMM sub-loop: GS ej x 4 STRIDED pairs per lane ----------
// Lane owns pairs {lane, lane+32, lane+64, lane+96} within the CTA tile:
// every obs load is LDG.64 with 32 contiguous lanes = 256B = 2 wavefronts.
// SLOT even -> 16B-aligned ulonglong2 weight loads from smem.
template <int GS, int SLOT, int EJB>
__device__ __forceinline__ void gemm_group(const u64* __restrict__ swd,
                                           const float* __restrict__ sbias,
                                           u64* __restrict__ sP,
                                           int pgbase, int lane) {
    u64 acc[4 * GS];
    #pragma unroll
    for (int k = 0; k < GS; k++) {
        u64 bv = dup2(sbias[EJB + k]);
        acc[4 * k] = bv; acc[4 * k + 1] = bv; acc[4 * k + 2] = bv; acc[4 * k + 3] = bv;
    }
    const u64* ob = reinterpret_cast<const u64*>(g_obsT) + pgbase + lane;
    u64 ovn[4];
    #pragma unroll
    for (int j = 0; j < 4; j++) ovn[j] = ob[j * 32];          // prefetch d=0
    #pragma unroll 4
    for (int d = 0; d < 64; d++) {
        u64 ov[4];
        #pragma unroll
        for (int j = 0; j < 4; j++) ov[j] = ovn[j];
        if (d < 63) {
            #pragma unroll
            for (int j = 0; j < 4; j++) ovn[j] = ob[(d + 1) * NPAIR + j * 32];
        }
        const u64* w = swd + d * WD_STRIDE + SLOT;
        const ulonglong2* w2 = reinterpret_cast<const ulonglong2*>(w);
        u64 wk[GS];
        #pragma unroll
        for (int k2 = 0; k2 < GS / 2; k2++) {
            ulonglong2 ww = w2[k2];
            wk[2 * k2] = ww.x; wk[2 * k2 + 1] = ww.y;
        }
        if (GS & 1) wk[GS - 1] = w[GS - 1];
        #pragma unroll
        for (int k = 0; k < GS; k++) {
            #pragma unroll
            for (int j = 0; j < 4; j++)
                acc[4 * k + j] = ffma2(ov[j], wk[k], acc[4 * k + j]);
        }
    }
    // coalesced STS.64: lanes contiguous per j-slice
    #pragma unroll
    for (int k = 0; k < GS; k++) {
        u64* dst = sP + (EJB + k) * PAIRS_CTA + lane;
        #pragma unroll
        for (int j = 0; j < 4; j++) dst[j * 32] = acc[4 * k + j];
    }
}

// smem layout (u64): swd[0,2688) stwd[2688,3184) sP[3184,8432) + bias/red
#define SMEM_U64   8432
#define SMEM_BYTES (SMEM_U64 * 8 + 48 * 4)

// ---------------- phase 2: warp-specialized GEMM + tail ----------------
// grid = (O_NUM, S_NUM, NBLK_B): bt is SLOWEST so CTAs co-resident on one SM
// share (at most 2) obs batch-slices -> obs stream stays L1-resident.
// ej groups 11/10/10/10: critical SMSP load 1.07x mean (was 1.17x with 12).
__global__ void __launch_bounds__(NTHR, 3)
eql_main(const float* __restrict__ constb, float* __restrict__ out) {
    extern __shared__ __align__(16) u64 sm[];
    u64* swd   = sm;             // [64][42] dup'd gemm weights (slotted)
    u64* stwd  = sm + 2688;      // [496] dup'd tail weights
    u64* sP    = sm + 3184;      // [41][128] pre-activations (batch pairs)
    float* sbias = reinterpret_cast<float*>(sm + SMEM_U64);
    float* sred  = sbias + 44;

    const int t  = threadIdx.x;
    const int o  = blockIdx.x;
    const int s  = blockIdx.y;
    const int bt = blockIdx.z;
    const int so = s * O_NUM + o;

    // ---- stage weights (coalesced 16B copies) ----
    {
        const ulonglong2* src =
            reinterpret_cast<const ulonglong2*>(g_wgemm + (size_t)so * 2688);
        ulonglong2* dst = reinterpret_cast<ulonglong2*>(swd);
        #pragma unroll
        for (int i = t; i < 1344; i += NTHR) dst[i] = src[i];
        src = reinterpret_cast<const ulonglong2*>(g_wtail + (size_t)so * 496);
        dst = reinterpret_cast<ulonglong2*>(stwd);
        #pragma unroll
        for (int i = t; i < 248; i += NTHR) dst[i] = src[i];
    }
    if (t < BSHAPE) sbias[t] = constb[o * BSHAPE + t];
    __syncthreads();

    // ---- GEMM phase: warp = ej-group (11/10/10/10), lane = 4 strided pairs -
    {
        const int wid = t >> 5, lane = t & 31;
        const int pgbase = bt * PAIRS_CTA;
        if      (wid == 0) gemm_group<11,  0,  0>(swd, sbias, sP, pgbase, lane);
        else if (wid == 1) gemm_group<10, 12, 11>(swd, sbias, sP, pgbase, lane);
        else if (wid == 2) gemm_group<10, 22, 21>(swd, sbias, sP, pgbase, lane);
        else               gemm_group<10, 32, 31>(swd, sbias, sP, pgbase, lane);
    }
    __syncthreads();

    // ---- tail phase: 1 pair per thread (all 128 threads) ----
    float racc = 0.0f;
    {
        const int p = t;
        u64 h[30];
        u64 ta[8];

        // L0: ej 0-5, mul x3
        h[0] = opk_mul(sP[0 * PAIRS_CTA + p], sP[1 * PAIRS_CTA + p], racc);
        h[1] = opk_mul(sP[2 * PAIRS_CTA + p], sP[3 * PAIRS_CTA + p], racc);
        h[2] = opk_mul(sP[4 * PAIRS_CTA + p], sP[5 * PAIRS_CTA + p], racc);

        // L1: ej 6-11 + tail(3 x 6), div x3
        #pragma unroll
        for (int e = 0; e < 6; e++) ta[e] = sP[(6 + e) * PAIRS_CTA + p];
        #pragma unroll
        for (int r = 0; r < 3; r++) {
            const u64* w = stwd + 0 + r * 6;
            #pragma unroll
            for (int e = 0; e < 6; e++) ta[e] = ffma2(h[r], w[e], ta[e]);
        }
        h[3] = opk_div(ta[0], ta[1], racc);
        h[4] = opk_div(ta[2], ta[3], racc);
        h[5] = opk_div(ta[4], ta[5], racc);

        // L2: ej 12-19 + tail(6 x 8)
        #pragma unroll
        for (int e = 0; e < 8; e++) ta[e] = sP[(12 + e) * PAIRS_CTA + p];
        #pragma unroll
        for (int r = 0; r < 6; r++) {
            const u64* w = stwd + 18 + r * 8;
            #pragma unroll
            for (int e = 0; e < 8; e++) ta[e] = ffma2(h[r], w[e], ta[e]);
        }
        h[6]  = opk_log(ta[0], racc);
        h[7]  = opk_log(ta[1], racc);
        h[8]  = opk_exp(ta[2], racc);
        h[9]  = opk_exp(ta[3], racc);
        h[10] = opk_sin(ta[4]);
        h[11] = opk_sin(ta[5]);
        h[12] = opk_cos(ta[6]);
        h[13] = opk_cos(ta[7]);

        // L3: ej 20-27 + tail(14 x 8)
        #pragma unroll
        for (int e = 0; e < 8; e++) ta[e] = sP[(20 + e) * PAIRS_CTA + p];
        #pragma unroll
        for (int r = 0; r < 14; r++) {
            const u64* w = stwd + 66 + r * 8;
            #pragma unroll
            for (int e = 0; e < 8; e++) ta[e] = ffma2(h[r], w[e], ta[e]);
        }
        h[14] = opk_log(ta[0], racc);
        h[15] = opk_log(ta[1], racc);
        h[16] = opk_exp(ta[2], racc);
        h[17] = opk_exp(ta[3], racc);
        h[18] = opk_sin(ta[4]);
        h[19] = opk_sin(ta[5]);
        h[20] = opk_cos(ta[6]);
        h[21] = opk_cos(ta[7]);

        // L4: ej 28-33 + tail(22 x 6)
        #pragma unroll
        for (int e = 0; e < 6; e++) ta[e] = sP[(28 + e) * PAIRS_CTA + p];
        #pragma unroll
        for (int r = 0; r < 22; r++) {
            const u64* w = stwd + 178 + r * 6;
            #pragma unroll
            for (int e = 0; e < 6; e++) ta[e] = ffma2(h[r], w[e], ta[e]);
        }
        h[22] = opk_mul(ta[0], ta[1], racc);
        h[23] = opk_div(ta[2], ta[3], racc);
        h[24] = opk_log(ta[4], racc);
        h[25] = opk_exp(ta[5], racc);

        // L5: ej 34-39 + tail(26 x 6)
        #pragma unroll
        for (int e = 0; e < 6; e++) ta[e] = sP[(34 + e) * PAIRS_CTA + p];
        #pragma unroll
        for (int r = 0; r < 26; r++) {
            const u64* w = stwd + 310 + r * 6;
            #pragma unroll
            for (int e = 0; e < 6; e++) ta[e] = ffma2(h[r], w[e], ta[e]);
        }
        h[26] = opk_mul(ta[0], ta[1], racc);
        h[27] = opk_div(ta[2], ta[3], racc);
        h[28] = opk_log(ta[4], racc);
        h[29] = opk_exp(ta[5], racc);

        // head: ej 40 + tail(30 x 1)
        u64 last = sP[40 * PAIRS_CTA + p];
        #pragma unroll
        for (int r = 0; r < 30; r++) last = ffma2(h[r], stwd[466 + r], last);

        float2 lv = unpk(last);
        const int b = bt * (2 * PAIRS_CTA) + 2 * p;
        out[((size_t)(s * BATCH + b))     * O_NUM + o] = lv.x;
        out[((size_t)(s * BATCH + b + 1)) * O_NUM + o] = lv.y;
    }

    // regu block reduction (deterministic)
    #pragma unroll
    for (int off = 16; off > 0; off >>= 1)
        racc += __shfl_down_sync(0xFFFFFFFFu, racc, off);
    if ((t & 31) == 0) sred[t >> 5] = racc;
    __syncthreads();
    if (t == 0) {
        float psum = (sred[0] + sred[1]) + (sred[2] + sred[3]);
        g_partials[so * NBLK_B + bt] = psum;
    }
}

// ---------------- phase 3: regu final reduce (shuffle, cheap) --------------
__global__ void eql_reduce(float* __restrict__ out) {
    __shared__ double sw[8];
    const int t = threadIdx.x;            // 256 threads
    double acc = 0.0;
    #pragma unroll
    for (int k = 0; k < NPART / 256; k++)
        acc += (double)g_partials[k * 256 + t];
    #pragma unroll
    for (int off = 16; off > 0; off >>= 1)
        acc += __shfl_down_sync(0xFFFFFFFFu, acc, off);
    if ((t & 31) == 0) sw[t >> 5] = acc;
    __syncthreads();
    if (t == 0) {
        double s = 0.0;
        #pragma unroll
        for (int i = 0; i < 8; i++) s += sw[i];
        out[TOTAL_ELEMS] = (float)(s / (double)TOTAL_ELEMS);
    }
}

// ---------------- launch ----------------
extern "C" void kernel_launch(void* const* d_in, const int* in_sizes, int n_in,
                              void* d_out, int out_size) {
    const float* obs    = (const float*)d_in[0];   // (4096, 64)
    const float* scores = (const float*)d_in[1];   // (15, 3120)
    const float* cwbase = (const float*)d_in[2];   // (15, 3120)
    const float* constb = (const float*)d_in[3];   // (15, 41)
    const float* u0     = (const float*)d_in[4];   // (16, 15, 3120)
    const float* u1     = (const float*)d_in[5];   // (16, 15, 3120)
    float* out = (float*)d_out;                    // 983040 outs + 1 regu

    cudaFuncSetAttribute(eql_main, cudaFuncAttributeMaxDynamicSharedMemorySize,
                         SMEM_BYTES);

    // 3 launches total: prepare (gate+transpose fused), main, reduce
    eql_prepare<<<NBLK_GATE + NBLK_TR, 256>>>(scores, cwbase, u0, u1, obs);

    dim3 grid(O_NUM, S_NUM, NBLK_B);               // (15, 16, 16) bt slowest
    eql_main<<<grid, NTHR, SMEM_BYTES>>>(constb, out);

    eql_reduce<<<1, 256>>>(out);
}

// round 17
// speedup vs baseline: 1.0218x; 1.0218x over previous
#include <cuda_runtime.h>
#include <math.h>

// ---------------- problem constants ----------------
#define S_NUM   16
#define O_NUM   15
#define BATCH   4096
#define N_IN    64
#define WSHAPE  3120
#define BSHAPE  41
#define TOTAL_ELEMS (S_NUM * BATCH * O_NUM)   // 983040
#define E_JOINT 41
#define SO_NUM  (S_NUM * O_NUM)               // 240
#define OW_NUM  (O_NUM * WSHAPE)              // 46800
#define NTHR    128
#define PAIRS_CTA 128                         // 256 batch per CTA (4 pairs/lane)
#define NPAIR   (BATCH / 2)                   // 2048
#define NBLK_B  (NPAIR / PAIRS_CTA)           // 16
#define NPART   (SO_NUM * NBLK_B)             // 3840
#define WD_STRIDE 42                          // u64 per dim row (41 ej + pad)
#define EPSF    1e-20f
#define TEMP    0.03f

#define NBLK_GATE ((OW_NUM + 255) / 256)            // 183
#define NBLK_TR   ((BATCH / 32) * (N_IN / 32))      // 256

typedef unsigned long long u64;

// scratch (allocation-free rule: __device__ globals)
__device__ __align__(16) float g_obsT[N_IN * BATCH];            // 1 MB
__device__ __align__(16) u64 g_wgemm[SO_NUM * 64 * WD_STRIDE];  // 5.2 MB dup'd
__device__ __align__(16) u64 g_wtail[SO_NUM * 496];             // 0.95 MB dup'd
__device__ float g_partials[NPART];

// ---------------- packed f32x2 helpers ----------------
__device__ __forceinline__ u64 pk(float lo, float hi) {
    u64 r; asm("mov.b64 %0, {%1, %2};" : "=l"(r) : "f"(lo), "f"(hi)); return r;
}
__device__ __forceinline__ float2 unpk(u64 v) {
    float2 f; asm("mov.b64 {%0, %1}, %2;" : "=f"(f.x), "=f"(f.y) : "l"(v)); return f;
}
__device__ __forceinline__ u64 dup2(float x) { return pk(x, x); }
__device__ __forceinline__ u64 ffma2(u64 a, u64 b, u64 c) {
    u64 d; asm("fma.rn.f32x2 %0, %1, %2, %3;" : "=l"(d) : "l"(a), "l"(b), "l"(c));
    return d;
}

// ---------------- phase 1 (single launch): gate->weights + obs transpose ----
// Gate blocks: ONE thread per ow; logit computed once (PRECISE, identical
// formula/rounding as before), then s-loop applies the 16 noise samples and
// scatters weights directly into final g_wgemm (slot==ej) / g_wtail layout.
// Trailing blocks: tiled obs transpose into g_obsT.
__global__ void eql_prepare(const float* __restrict__ scores,
                            const float* __restrict__ base,
                            const float* __restrict__ u0,
                            const float* __restrict__ u1,
                            const float* __restrict__ obs) {
    if (blockIdx.x < NBLK_GATE) {
        int ow = blockIdx.x * 256 + threadIdx.x;
        if (ow >= OW_NUM) return;
        int widx = ow % WSHAPE;

        // logit: computed ONCE per ow (was 16x) — bit-identical math
        float sc    = scores[ow];
        float cs    = 1.0f / (1.0f + expf(-sc));
        float logit = logf(cs + EPSF) - logf(1.0f - cs + EPSF);
        float bw    = base[ow];

        // route widx -> (seg, d, e) once
        int seg;
        if (widx < 1346) seg = (widx < 384) ? 0 : ((widx < 786) ? 1 : 2);
        else if (widx < 2486) seg = (widx < 1970) ? 3 : 4;
        else seg = (widx < 3026) ? 5 : 6;
        const int S_[7]   = {0, 384, 786, 1346, 1970, 2486, 3026};
        const int INL[7]  = {6, 6, 8, 8, 6, 6, 1};
        const int EJB_[7] = {0, 6, 12, 20, 28, 34, 40};
        const int TB_[7]  = {0, 0, 18, 66, 178, 310, 466};
        int r = widx - S_[seg];
        int d = r / INL[seg], e = r % INL[seg];
        bool isg = (d < 64);
        size_t off0 = isg
            ? (size_t)(d * WD_STRIDE + EJB_[seg] + e)
            : (size_t)(TB_[seg] + (d - 64) * INL[seg] + e);
        int o = ow / WSHAPE;

        #pragma unroll 4
        for (int s = 0; s < S_NUM; s++) {
            int i  = s * OW_NUM + ow;
            int so = s * O_NUM + o;
            float noise = -logf(logf(u0[i] + EPSF) / logf(u1[i] + EPSF) + EPSF);
            float z     = (logit + noise) * TEMP;
            float soft  = 1.0f / (1.0f + expf(-z));
            float hard  = (soft > 0.5f) ? 1.0f : 0.0f;
            u64 wd = dup2(bw * ((hard - soft) + soft));
            if (isg) g_wgemm[(size_t)so * (64 * WD_STRIDE) + off0] = wd;
            else     g_wtail[(size_t)so * 496 + off0] = wd;
        }
    } else {
        // obs transpose: emulate (32,8) block over 256 threads
        __shared__ float tile[32][33];
        int blk = blockIdx.x - NBLK_GATE;
        int bx = (blk & (BATCH / 32 - 1)) * 32;   // batch base
        int dx = (blk >> 7) * 32;                 // dim base (BATCH/32 = 128)
        int tx = threadIdx.x & 31, ty = threadIdx.x >> 5;  // (32, 8)
        #pragma unroll
        for (int j = 0; j < 32; j += 8)
            tile[ty + j][tx] = obs[(size_t)(bx + ty + j) * N_IN + dx + tx];
        __syncthreads();
        #pragma unroll
        for (int j = 0; j < 32; j += 8)
            g_obsT[(size_t)(dx + ty + j) * BATCH + bx + tx] = tile[tx][ty + j];
    }
}

// ---------------- scalar ops (fast intrinsics; validated rel_err 3.8e-5) ---
__device__ __forceinline__ float op_mul(float a, float b, float& r) {
    r += fmaxf(-100.0f - a, 0.0f) + fmaxf(a - 100.0f, 0.0f)
       + fmaxf(-100.0f - b, 0.0f) + fmaxf(b - 100.0f, 0.0f);
    return fminf(fmaxf(a, -100.0f), 100.0f) * fminf(fmaxf(b, -100.0f), 100.0f);
}
__device__ __forceinline__ float op_div(float a, float b, float& r) {
    r += fmaxf(0.01f - b, 0.0f);
    return (b < 0.01f) ? 0.0f : __fdividef(a, b);
}
__device__ __forceinline__ float op_log(float a, float& r) {
    r += fmaxf(0.001f - a, 0.0f);
    return __logf(fmaxf(a, 0.001f));
}
__device__ __forceinline__ float op_exp(float a, float& r) {
    r += fmaxf(-10.0f - a, 0.0f) + fmaxf(a - 4.0f, 0.0f);
    return __expf(fminf(fmaxf(a, -10.0f), 4.0f));
}
__device__ __forceinline__ u64 opk_mul(u64 A, u64 B, float& r) {
    float2 a = unpk(A), b = unpk(B);
    return pk(op_mul(a.x, b.x, r), op_mul(a.y, b.y, r));
}
__device__ __forceinline__ u64 opk_div(u64 A, u64 B, float& r) {
    float2 a = unpk(A), b = unpk(B);
    return pk(op_div(a.x, b.x, r), op_div(a.y, b.y, r));
}
__device__ __forceinline__ u64 opk_log(u64 A, float& r) {
    float2 a = unpk(A); return pk(op_log(a.x, r), op_log(a.y, r));
}
__device__ __forceinline__ u64 opk_exp(u64 A, float& r) {
    float2 a = unpk(A); return pk(op_exp(a.x, r), op_exp(a.y, r));
}
__device__ __forceinline__ u64 opk_sin(u64 A) {
    float2 a = unpk(A); return pk(__sinf(a.x), __sinf(a.y));
}
__device__ __forceinline__ u64 opk_cos(u64 A) {
    float2 a = unpk(A); return pk(__cosf(a.x), __cosf(a.y));
}

// ---------------- GEMM sub-loop: GS ej x 4 STRIDED pairs per lane ----------
// Lane owns pairs {lane, lane+32, lane+64, lane+96} within the CTA tile:
// every obs load is LDG.64 with 32 contiguous lanes = 256B = 2 wavefronts.
template <int GS, int EJ0>
__device__ __forceinline__ void gemm_group(const u64* __restrict__ swd,
                                           const float* __restrict__ sbias,
                                           u64* __restrict__ sP,
                                           int pgbase, int lane) {
    u64 acc[4 * GS];
    #pragma unroll
    for (int k = 0; k < GS; k++) {
        u64 bv = dup2(sbias[EJ0 + k]);
        acc[4 * k] = bv; acc[4 * k + 1] = bv; acc[4 * k + 2] = bv; acc[4 * k + 3] = bv;
    }
    const u64* ob = reinterpret_cast<const u64*>(g_obsT) + pgbase + lane;
    u64 ovn[4];
    #pragma unroll
    for (int j = 0; j < 4; j++) ovn[j] = ob[j * 32];          // prefetch d=0
    #pragma unroll 4
    for (int d = 0; d < 64; d++) {
        u64 ov[4];
        #pragma unroll
        for (int j = 0; j < 4; j++) ov[j] = ovn[j];
        if (d < 63) {
            #pragma unroll
            for (int j = 0; j < 4; j++) ovn[j] = ob[(d + 1) * NPAIR + j * 32];
        }
        const u64* w = swd + d * WD_STRIDE + EJ0;
        const ulonglong2* w2 = reinterpret_cast<const ulonglong2*>(w);
        u64 wk[GS];
        #pragma unroll
        for (int k2 = 0; k2 < GS / 2; k2++) {
            ulonglong2 ww = w2[k2];
            wk[2 * k2] = ww.x; wk[2 * k2 + 1] = ww.y;
        }
        if (GS & 1) wk[GS - 1] = w[GS - 1];
        #pragma unroll
        for (int k = 0; k < GS; k++) {
            #pragma unroll
            for (int j = 0; j < 4; j++)
                acc[4 * k + j] = ffma2(ov[j], wk[k], acc[4 * k + j]);
        }
    }
    // coalesced STS.64: lanes contiguous per j-slice
    #pragma unroll
    for (int k = 0; k < GS; k++) {
        u64* dst = sP + (EJ0 + k) * PAIRS_CTA + lane;
        #pragma unroll
        for (int j = 0; j < 4; j++) dst[j * 32] = acc[4 * k + j];
    }
}

// smem layout (u64): swd[0,2688) stwd[2688,3184) sP[3184,8432) + bias/red
#define SMEM_U64   8432
#define SMEM_BYTES (SMEM_U64 * 8 + 48 * 4)

// ---------------- phase 2: warp-specialized GEMM + tail ----------------
// grid = (O_NUM, S_NUM, NBLK_B): bt is SLOWEST so CTAs co-resident on one SM
// share (at most 2) obs batch-slices -> obs stream stays L1-resident.
__global__ void __launch_bounds__(NTHR, 3)
eql_main(const float* __restrict__ constb, float* __restrict__ out) {
    extern __shared__ __align__(16) u64 sm[];
    u64* swd   = sm;             // [64][42] dup'd gemm weights
    u64* stwd  = sm + 2688;      // [496] dup'd tail weights
    u64* sP    = sm + 3184;      // [41][128] pre-activations (batch pairs)
    float* sbias = reinterpret_cast<float*>(sm + SMEM_U64);
    float* sred  = sbias + 44;

    const int t  = threadIdx.x;
    const int o  = blockIdx.x;
    const int s  = blockIdx.y;
    const int bt = blockIdx.z;
    const int so = s * O_NUM + o;

    // ---- stage weights (coalesced 16B copies) ----
    {
        const ulonglong2* src =
            reinterpret_cast<const ulonglong2*>(g_wgemm + (size_t)so * 2688);
        ulonglong2* dst = reinterpret_cast<ulonglong2*>(swd);
        #pragma unroll
        for (int i = t; i < 1344; i += NTHR) dst[i] = src[i];
        src = reinterpret_cast<const ulonglong2*>(g_wtail + (size_t)so * 496);
        dst = reinterpret_cast<ulonglong2*>(stwd);
        #pragma unroll
        for (int i = t; i < 248; i += NTHR) dst[i] = src[i];
    }
    if (t < BSHAPE) sbias[t] = constb[o * BSHAPE + t];
    __syncthreads();

    // ---- GEMM phase: warp = ej-group (12/10/10/9), lane = 4 strided pairs --
    {
        const int wid = t >> 5, lane = t & 31;
        const int pgbase = bt * PAIRS_CTA;
        if      (wid == 0) gemm_group<12,  0>(swd, sbias, sP, pgbase, lane);
        else if (wid == 1) gemm_group<10, 12>(swd, sbias, sP, pgbase, lane);
        else if (wid == 2) gemm_group<10, 22>(swd, sbias, sP, pgbase, lane);
        else               gemm_group< 9, 32>(swd, sbias, sP, pgbase, lane);
    }
    __syncthreads();

    // ---- tail phase: 1 pair per thread (all 128 threads) ----
    float racc = 0.0f;
    {
        const int p = t;
        u64 h[30];
        u64 ta[8];

        // L0: ej 0-5, mul x3
        h[0] = opk_mul(sP[0 * PAIRS_CTA + p], sP[1 * PAIRS_CTA + p], racc);
        h[1] = opk_mul(sP[2 * PAIRS_CTA + p], sP[3 * PAIRS_CTA + p], racc);
        h[2] = opk_mul(sP[4 * PAIRS_CTA + p], sP[5 * PAIRS_CTA + p], racc);

        // L1: ej 6-11 + tail(3 x 6), div x3
        #pragma unroll
        for (int e = 0; e < 6; e++) ta[e] = sP[(6 + e) * PAIRS_CTA + p];
        #pragma unroll
        for (int r = 0; r < 3; r++) {
            const u64* w = stwd + 0 + r * 6;
            #pragma unroll
            for (int e = 0; e < 6; e++) ta[e] = ffma2(h[r], w[e], ta[e]);
        }
        h[3] = opk_div(ta[0], ta[1], racc);
        h[4] = opk_div(ta[2], ta[3], racc);
        h[5] = opk_div(ta[4], ta[5], racc);

        // L2: ej 12-19 + tail(6 x 8)
        #pragma unroll
        for (int e = 0; e < 8; e++) ta[e] = sP[(12 + e) * PAIRS_CTA + p];
        #pragma unroll
        for (int r = 0; r < 6; r++) {
            const u64* w = stwd + 18 + r * 8;
            #pragma unroll
            for (int e = 0; e < 8; e++) ta[e] = ffma2(h[r], w[e], ta[e]);
        }
        h[6]  = opk_log(ta[0], racc);
        h[7]  = opk_log(ta[1], racc);
        h[8]  = opk_exp(ta[2], racc);
        h[9]  = opk_exp(ta[3], racc);
        h[10] = opk_sin(ta[4]);
        h[11] = opk_sin(ta[5]);
        h[12] = opk_cos(ta[6]);
        h[13] = opk_cos(ta[7]);

        // L3: ej 20-27 + tail(14 x 8)
        #pragma unroll
        for (int e = 0; e < 8; e++) ta[e] = sP[(20 + e) * PAIRS_CTA + p];
        #pragma unroll
        for (int r = 0; r < 14; r++) {
            const u64* w = stwd + 66 + r * 8;
            #pragma unroll
            for (int e = 0; e < 8; e++) ta[e] = ffma2(h[r], w[e], ta[e]);
        }
        h[14] = opk_log(ta[0], racc);
        h[15] = opk_log(ta[1], racc);
        h[16] = opk_exp(ta[2], racc);
        h[17] = opk_exp(ta[3], racc);
        h[18] = opk_sin(ta[4]);
        h[19] = opk_sin(ta[5]);
        h[20] = opk_cos(ta[6]);
        h[21] = opk_cos(ta[7]);

        // L4: ej 28-33 + tail(22 x 6)
        #pragma unroll
        for (int e = 0; e < 6; e++) ta[e] = sP[(28 + e) * PAIRS_CTA + p];
        #pragma unroll
        for (int r = 0; r < 22; r++) {
            const u64* w = stwd + 178 + r * 6;
            #pragma unroll
            for (int e = 0; e < 6; e++) ta[e] = ffma2(h[r], w[e], ta[e]);
        }
        h[22] = opk_mul(ta[0], ta[1], racc);
        h[23] = opk_div(ta[2], ta[3], racc);
        h[24] = opk_log(ta[4], racc);
        h[25] = opk_exp(ta[5], racc);

        // L5: ej 34-39 + tail(26 x 6)
        #pragma unroll
        for (int e = 0; e < 6; e++) ta[e] = sP[(34 + e) * PAIRS_CTA + p];
        #pragma unroll
        for (int r = 0; r < 26; r++) {
            const u64* w = stwd + 310 + r * 6;
            #pragma unroll
            for (int e = 0; e < 6; e++) ta[e] = ffma2(h[r], w[e], ta[e]);
        }
        h[26] = opk_mul(ta[0], ta[1], racc);
        h[27] = opk_div(ta[2], ta[3], racc);
        h[28] = opk_log(ta[4], racc);
        h[29] = opk_exp(ta[5], racc);

        // head: ej 40 + tail(30 x 1)
        u64 last = sP[40 * PAIRS_CTA + p];
        #pragma unroll
        for (int r = 0; r < 30; r++) last = ffma2(h[r], stwd[466 + r], last);

        float2 lv = unpk(last);
        const int b = bt * (2 * PAIRS_CTA) + 2 * p;
        out[((size_t)(s * BATCH + b))     * O_NUM + o] = lv.x;
        out[((size_t)(s * BATCH + b + 1)) * O_NUM + o] = lv.y;
    }

    // regu block reduction (deterministic)
    #pragma unroll
    for (int off = 16; off > 0; off >>= 1)
        racc += __shfl_down_sync(0xFFFFFFFFu, racc, off);
    if ((t & 31) == 0) sred[t >> 5] = racc;
    __syncthreads();
    if (t == 0) {
        float psum = (sred[0] + sred[1]) + (sred[2] + sred[3]);
        g_partials[so * NBLK_B + bt] = psum;
    }
}

// ---------------- phase 3: regu final reduce (shuffle, cheap) --------------
__global__ void eql_reduce(float* __restrict__ out) {
    __shared__ double sw[8];
    const int t = threadIdx.x;            // 256 threads
    double acc = 0.0;
    #pragma unroll
    for (int k = 0; k < NPART / 256; k++)
        acc += (double)g_partials[k * 256 + t];
    #pragma unroll
    for (int off = 16; off > 0; off >>= 1)
        acc += __shfl_down_sync(0xFFFFFFFFu, acc, off);
    if ((t & 31) == 0) sw[t >> 5] = acc;
    __syncthreads();
    if (t == 0) {
        double s = 0.0;
        #pragma unroll
        for (int i = 0; i < 8; i++) s += sw[i];
        out[TOTAL_ELEMS] = (float)(s / (double)TOTAL_ELEMS);
    }
}

// ---------------- launch ----------------
extern "C" void kernel_launch(void* const* d_in, const int* in_sizes, int n_in,
                              void* d_out, int out_size) {
    const float* obs    = (const float*)d_in[0];   // (4096, 64)
    const float* scores = (const float*)d_in[1];   // (15, 3120)
    const float* cwbase = (const float*)d_in[2];   // (15, 3120)
    const float* constb = (const float*)d_in[3];   // (15, 41)
    const float* u0     = (const float*)d_in[4];   // (16, 15, 3120)
    const float* u1     = (const float*)d_in[5];   // (16, 15, 3120)
    float* out = (float*)d_out;                    // 983040 outs + 1 regu

    cudaFuncSetAttribute(eql_main, cudaFuncAttributeMaxDynamicSharedMemorySize,
                         SMEM_BYTES);

    // 3 launches total: prepare (gate+transpose fused), main, reduce
    eql_prepare<<<NBLK_GATE + NBLK_TR, 256>>>(scores, cwbase, u0, u1, obs);

    dim3 grid(O_NUM, S_NUM, NBLK_B);               // (15, 16, 16) bt slowest
    eql_main<<<grid, NTHR, SMEM_BYTES>>>(constb, out);

    eql_reduce<<<1, 256>>>(out);
}